// round 5
// baseline (speedup 1.0000x reference)
#include <cuda_runtime.h>

#define SQ   1024
#define DH   64
#define NBH  32

__device__ float g_partial[8 * NBH * SQ];   // [kblk][bh*SQ + row]
__device__ float g_rinv[NBH * SQ];

// Packed f32x2 helpers (B300 double-rate fp32; only reachable via PTX)
#define PACK2(dst, lo, hi) \
    asm("mov.b64 %0, {%1, %2};" : "=l"(dst) : "r"(lo), "r"(hi))
#define FMA2(d, a, b, c) \
    asm("fma.rn.f32x2 %0, %1, %2, %3;" : "=l"(d) : "l"(a), "l"(b), "l"(c))
#define UNPK2(lo, hi, src) \
    asm("mov.b64 {%0, %1}, %2;" : "=r"(lo), "=r"(hi) : "l"(src))

// ---------------------------------------------------------------------------
// Kernel 1: E = exp(QK^T/8 + ia_type + ia_feat), mask->0, into attn region.
// 128q x 128k tile, 256 threads, 8x8 output per thread via 8x4 f32x2 pairs.
// ---------------------------------------------------------------------------
__global__ __launch_bounds__(256, 2) void k_scores(
    const float* __restrict__ Q, const float* __restrict__ K,
    const float* __restrict__ iat, const float* __restrict__ iaf,
    const unsigned int* __restrict__ mask, float* __restrict__ E)
{
    const int kb = blockIdx.x;
    const int qb = blockIdx.y;
    const int bh = blockIdx.z;

    extern __shared__ float sm[];
    float* Qs = sm;                    // 128 x 68
    float* Ks = sm + 128 * 68;         // 128 x 68

    const int tid  = threadIdx.x;
    const int tx   = tid & 15;
    const int ty   = tid >> 4;
    const int lane = tid & 31;
    const int w    = tid >> 5;

    const float* Qg = Q + ((size_t)bh * SQ + (size_t)qb * 128) * DH;
    const float* Kg = K + ((size_t)bh * SQ + (size_t)kb * 128) * DH;

#pragma unroll
    for (int it = 0; it < 8; it++) {
        int f4  = tid + it * 256;
        int row = f4 >> 4;
        int c4  = (f4 & 15) << 2;
        *(float4*)(Qs + row * 68 + c4) = *(const float4*)(Qg + row * DH + c4);
        *(float4*)(Ks + row * 68 + c4) = *(const float4*)(Kg + row * DH + c4);
    }
    __syncthreads();

    // acc2[i][p] = (cols tx + 2p*16, tx + 2p*16 + 16) for row ty + i*16
    unsigned long long acc2[8][4];
#pragma unroll
    for (int i = 0; i < 8; i++)
#pragma unroll
        for (int p = 0; p < 4; p++) acc2[i][p] = 0ull;

#pragma unroll 2
    for (int d = 0; d < DH; d++) {
        unsigned int qv[8], kv[8];
        unsigned long long qq[8], kk[4];
#pragma unroll
        for (int i = 0; i < 8; i++)
            qv[i] = __float_as_uint(Qs[(ty + i * 16) * 68 + d]);
#pragma unroll
        for (int j = 0; j < 8; j++)
            kv[j] = __float_as_uint(Ks[(tx + j * 16) * 68 + d]);
#pragma unroll
        for (int i = 0; i < 8; i++) PACK2(qq[i], qv[i], qv[i]);
#pragma unroll
        for (int p = 0; p < 4; p++) PACK2(kk[p], kv[2 * p], kv[2 * p + 1]);
#pragma unroll
        for (int i = 0; i < 8; i++)
#pragma unroll
            for (int p = 0; p < 4; p++)
                FMA2(acc2[i][p], qq[i], kk[p], acc2[i][p]);
    }
    __syncthreads();

    // Stage accumulators through smem (stride 132: float4-aligned rows)
    float* Ss = sm;                    // 128 x 132 = 67584 B
#pragma unroll
    for (int i = 0; i < 8; i++)
#pragma unroll
        for (int p = 0; p < 4; p++) {
            unsigned int lo, hi;
            UNPK2(lo, hi, acc2[i][p]);
            Ss[(ty + i * 16) * 132 + tx + 2 * p * 16]      = __uint_as_float(lo);
            Ss[(ty + i * 16) * 132 + tx + 2 * p * 16 + 16] = __uint_as_float(hi);
        }
    __syncthreads();

    // Coalesced epilogue: one warp = one full 128-wide row per iteration
    const size_t base = (((size_t)bh * SQ) + (size_t)qb * 128) * SQ
                      + (size_t)kb * 128;
#pragma unroll 4
    for (int it = 0; it < 16; it++) {
        const int row = it * 8 + w;
        const int c   = lane << 2;
        const size_t g = base + (size_t)row * SQ + c;
        float4 a  = *(const float4*)(iat + g);
        float4 b  = *(const float4*)(iaf + g);
        uint4  m  = *(const uint4*)(mask + g);
        float4 sv = *(const float4*)(Ss + row * 132 + c);
        float4 e;
        e.x = m.x ? 0.f : __expf(fmaf(sv.x, 0.125f, a.x + b.x));
        e.y = m.y ? 0.f : __expf(fmaf(sv.y, 0.125f, a.y + b.y));
        e.z = m.z ? 0.f : __expf(fmaf(sv.z, 0.125f, a.z + b.z));
        e.w = m.w ? 0.f : __expf(fmaf(sv.w, 0.125f, a.w + b.w));
        *(float4*)(E + g) = e;

        float part = (e.x + e.y) + (e.z + e.w);
#pragma unroll
        for (int o = 16; o > 0; o >>= 1)
            part += __shfl_xor_sync(0xffffffffu, part, o);
        if (lane == 0)
            g_partial[(size_t)kb * (NBH * SQ) + (size_t)bh * SQ
                      + (size_t)qb * 128 + row] = part;
    }
}

// ---------------------------------------------------------------------------
__global__ __launch_bounds__(256) void k_rowsum()
{
    const int r = blockIdx.x * 256 + threadIdx.x;
    float s = 0.f;
#pragma unroll
    for (int kb = 0; kb < 8; kb++) s += g_partial[kb * (NBH * SQ) + r];
    g_rinv[r] = 1.f / s;
}

// ---------------------------------------------------------------------------
// Kernel 2: normalize attn in place + context = rinv * (E @ V).
// 64q x 64d tile, k-tiles of 128, 256 threads, 4x4 output via 4x2 f32x2 pairs.
// ---------------------------------------------------------------------------
__global__ __launch_bounds__(256, 3) void k_pv(
    const float* __restrict__ V, float* __restrict__ attn,
    float* __restrict__ ctx)
{
    const int qb = blockIdx.x;   // 0..15
    const int bh = blockIdx.y;   // 0..31

    extern __shared__ float sm[];
    float* Es  = sm;                               // 64 x 132
    float* Vs  = sm + 64 * 132;                    // 128 x 68
    float* sRi = sm + 64 * 132 + 128 * 68;         // 64

    const int tid  = threadIdx.x;
    const int tx   = tid & 15;   // cols tx*4 .. tx*4+3
    const int ty   = tid >> 4;   // rows ty*4 .. ty*4+3
    const int lane = tid & 31;
    const int w    = tid >> 5;

    if (tid < 64)
        sRi[tid] = g_rinv[(size_t)bh * SQ + (size_t)qb * 64 + tid];
    __syncthreads();

    unsigned long long acc2[4][2];   // [i][0]: cols tx*4+{0,1}, [i][1]: +{2,3}
#pragma unroll
    for (int i = 0; i < 4; i++) { acc2[i][0] = 0ull; acc2[i][1] = 0ull; }

    for (int kt = 0; kt < 8; kt++) {
        __syncthreads();
        const size_t ebase = (((size_t)bh * SQ) + (size_t)qb * 64) * SQ
                           + (size_t)kt * 128;
        // E tile 64x128, fused normalized write-back
#pragma unroll
        for (int it = 0; it < 8; it++) {
            const int row = it * 8 + w;
            const int c   = lane << 2;
            const size_t g = ebase + (size_t)row * SQ + c;
            float4 v = *(const float4*)(attn + g);
            *(float4*)(Es + row * 132 + c) = v;
            const float rv = sRi[row];
            v.x *= rv; v.y *= rv; v.z *= rv; v.w *= rv;
            *(float4*)(attn + g) = v;
        }
        // V tile 128x64
        const float* Vg = V + ((size_t)bh * SQ + (size_t)kt * 128) * DH;
#pragma unroll
        for (int it = 0; it < 8; it++) {
            int f4  = tid + it * 256;
            int row = f4 >> 4;
            int c4  = (f4 & 15) << 2;
            *(float4*)(Vs + row * 68 + c4) = *(const float4*)(Vg + row * DH + c4);
        }
        __syncthreads();

#pragma unroll 4
        for (int k = 0; k < 128; k++) {
            unsigned long long evv[4], v01, v23;
#pragma unroll
            for (int i = 0; i < 4; i++) {
                unsigned int u = __float_as_uint(Es[(ty * 4 + i) * 132 + k]);
                PACK2(evv[i], u, u);
            }
            float4 vv = *(const float4*)(Vs + k * 68 + tx * 4);
            PACK2(v01, __float_as_uint(vv.x), __float_as_uint(vv.y));
            PACK2(v23, __float_as_uint(vv.z), __float_as_uint(vv.w));
#pragma unroll
            for (int i = 0; i < 4; i++) {
                FMA2(acc2[i][0], evv[i], v01, acc2[i][0]);
                FMA2(acc2[i][1], evv[i], v23, acc2[i][1]);
            }
        }
    }

    // Epilogue: unpack, scale by rinv, float4 store
#pragma unroll
    for (int i = 0; i < 4; i++) {
        const int r = ty * 4 + i;
        const float rv = sRi[r];
        const size_t ob = (((size_t)bh * SQ) + (size_t)qb * 64 + r) * DH;
        unsigned int x, y, z, ww;
        UNPK2(x, y, acc2[i][0]);
        UNPK2(z, ww, acc2[i][1]);
        float4 o;
        o.x = __uint_as_float(x) * rv;
        o.y = __uint_as_float(y) * rv;
        o.z = __uint_as_float(z) * rv;
        o.w = __uint_as_float(ww) * rv;
        *(float4*)(ctx + ob + tx * 4) = o;
    }
}

// ---------------------------------------------------------------------------
extern "C" void kernel_launch(void* const* d_in, const int* in_sizes, int n_in,
                              void* d_out, int out_size)
{
    const float*        Q    = (const float*)d_in[0];
    const float*        K    = (const float*)d_in[1];
    const float*        V    = (const float*)d_in[2];
    const unsigned int* mask = (const unsigned int*)d_in[4];  // attn_mask_if
    const float*        iat  = (const float*)d_in[5];
    const float*        iaf  = (const float*)d_in[6];

    float* ctx  = (float*)d_out;
    float* attn = ctx + (size_t)NBH * SQ * DH;

    const int smem1 = 2 * 128 * 68 * 4;                         // 69632 B
    const int smem2 = (64 * 132 + 128 * 68 + 64) * 4;           // 68864 B
    cudaFuncSetAttribute(k_scores, cudaFuncAttributeMaxDynamicSharedMemorySize, smem1);
    cudaFuncSetAttribute(k_pv,     cudaFuncAttributeMaxDynamicSharedMemorySize, smem2);

    dim3 g1(8, 8, NBH);
    k_scores<<<g1, 256, smem1>>>(Q, K, iat, iaf, mask, attn);

    k_rowsum<<<(NBH * SQ) / 256, 256>>>();

    dim3 g2(16, NBH);
    k_pv<<<g2, 256, smem2>>>(V, attn, ctx);
}